// round 9
// baseline (speedup 1.0000x reference)
#include <cuda_runtime.h>
#include <cstdint>

// Fused 3x3 dilate (max) + erode (min), fp32, (8,32,512,512) NCHW.
// Border: reduce over valid pixels only (replication == +/-inf pad).
// Output: [dilated | eroded], each 67108864 floats.
//
// R9: R6 skeleton (bulk-async reads, STG.cs stores, 2 chunks/block),
//     chunk size doubled: 16 output rows / 18 input rows per chunk.
//  - 36.9KB per stage, 2 stages -> 73.9KB dynamic smem, 3 blocks/SM.
//  - Launch-time in-flight reads ~221KB/SM; halo fraction 2/16; half the
//    mbarrier round-trips of R6; grid 4096.

#define W 512
#define H 512
#define ROWS_OUT 16
#define ROWS_IN  18
#define THREADS 128
#define STAGE_FLOATS (ROWS_IN * W)              // 9216
#define STAGE_BYTES  (STAGE_FLOATS * 4)         // 36864
#define SMEM_TOTAL   (2 * STAGE_BYTES + 64)

extern __shared__ float smem_pool[];

__device__ __forceinline__ void stcs4(float* p, float4 v) {
    asm volatile("st.global.cs.v4.f32 [%0], {%1,%2,%3,%4};"
                 :: "l"(p), "f"(v.x), "f"(v.y), "f"(v.z), "f"(v.w) : "memory");
}

__device__ __forceinline__ void mbar_wait(uint32_t mbar, uint32_t parity) {
    asm volatile(
        "{\n\t"
        ".reg .pred P;\n\t"
        "WAIT_%=:\n\t"
        "mbarrier.try_wait.parity.shared.b64 P, [%0], %1, 10000000;\n\t"
        "@P bra.uni DONE_%=;\n\t"
        "bra.uni WAIT_%=;\n\t"
        "DONE_%=:\n\t"
        "}"
        :: "r"(mbar), "r"(parity) : "memory");
}

__device__ __forceinline__ void bulk_load(uint32_t s_data, const float* src,
                                          uint32_t s_mbar) {
    asm volatile("mbarrier.arrive.expect_tx.shared.b64 _, [%0], %1;"
                 :: "r"(s_mbar), "r"((uint32_t)STAGE_BYTES));
    asm volatile(
        "cp.async.bulk.shared::cluster.global.mbarrier::complete_tx::bytes "
        "[%0], [%1], %2, [%3];"
        :: "r"(s_data), "l"(src), "r"((uint32_t)STAGE_BYTES), "r"(s_mbar)
        : "memory");
}

__device__ __forceinline__ void compute_chunk(const float* __restrict__ buf,
                                              int r0, int y0, int x4,
                                              float* __restrict__ dbase,
                                              float* __restrict__ ebase)
{
    auto read_row = [&](int si, float4& v, float& lv, float& rv) {
        const float* rp = buf + si * W;
        v  = *reinterpret_cast<const float4*>(rp + x4);
        lv = (x4 > 0)     ? rp[x4 - 1] : v.x;   // replicate at image edge
        rv = (x4 + 4 < W) ? rp[x4 + 4] : v.w;
    };

    float4 pv, cv, nv;
    float plv, prv, clv, crv, nlv, nrv;

    int sp = r0 - 1 - y0; if (sp < 0) sp = 0;       // replicate top row
    read_row(sp,      pv, plv, prv);
    read_row(r0 - y0, cv, clv, crv);

    float* drow = dbase + (size_t)r0 * W + x4;
    float* erow = ebase + (size_t)r0 * W + x4;

    #pragma unroll
    for (int i = 0; i < ROWS_OUT; ++i) {
        int sn = r0 + i + 1 - y0;
        if (sn > ROWS_IN - 1) sn = ROWS_IN - 1;     // replicate bottom row
        read_row(sn, nv, nlv, nrv);

        float4 vmn, vmx;
        vmn.x = fminf(pv.x, fminf(cv.x, nv.x));
        vmn.y = fminf(pv.y, fminf(cv.y, nv.y));
        vmn.z = fminf(pv.z, fminf(cv.z, nv.z));
        vmn.w = fminf(pv.w, fminf(cv.w, nv.w));
        vmx.x = fmaxf(pv.x, fmaxf(cv.x, nv.x));
        vmx.y = fmaxf(pv.y, fmaxf(cv.y, nv.y));
        vmx.z = fmaxf(pv.z, fmaxf(cv.z, nv.z));
        vmx.w = fmaxf(pv.w, fmaxf(cv.w, nv.w));

        const float vl_mn = fminf(plv, fminf(clv, nlv));
        const float vl_mx = fmaxf(plv, fmaxf(clv, nlv));
        const float vr_mn = fminf(prv, fminf(crv, nrv));
        const float vr_mx = fmaxf(prv, fmaxf(crv, nrv));

        float4 omin, omax;
        omin.x = fminf(vl_mn, fminf(vmn.x, vmn.y));
        omin.y = fminf(vmn.x, fminf(vmn.y, vmn.z));
        omin.z = fminf(vmn.y, fminf(vmn.z, vmn.w));
        omin.w = fminf(vmn.z, fminf(vmn.w, vr_mn));

        omax.x = fmaxf(vl_mx, fmaxf(vmx.x, vmx.y));
        omax.y = fmaxf(vmx.x, fmaxf(vmx.y, vmx.z));
        omax.z = fmaxf(vmx.y, fmaxf(vmx.z, vmx.w));
        omax.w = fmaxf(vmx.z, fmaxf(vmx.w, vr_mx));

        stcs4(drow, omax);
        stcs4(erow, omin);
        drow += W;
        erow += W;

        pv = cv; cv = nv;
        plv = clv; clv = nlv;
        prv = crv; crv = nrv;
    }
}

__global__ __launch_bounds__(THREADS)
void erode_dilate_kernel(const float* __restrict__ in,
                         float* __restrict__ dil,
                         float* __restrict__ ero)
{
    float* stage0 = smem_pool;
    float* stage1 = smem_pool + STAGE_FLOATS;
    uint64_t* mbar = (uint64_t*)(smem_pool + 2 * STAGE_FLOATS);

    const int tid = threadIdx.x;
    const int x4  = tid * 4;
    const int bid = blockIdx.x;

    // two consecutive 16-row chunks of one image (16 pairs per image)
    const int img = bid >> 4;
    const int pr  = bid & 15;
    const int r0a = pr * (ROWS_OUT * 2);
    const int r0b = r0a + ROWS_OUT;

    int y0a = r0a - 1;
    if (y0a < 0) y0a = 0;
    if (y0a > H - ROWS_IN) y0a = H - ROWS_IN;
    int y0b = r0b - 1;
    if (y0b > H - ROWS_IN) y0b = H - ROWS_IN;

    const size_t ibase = (size_t)img * (H * W);
    const float* base  = in  + ibase;
    float*       dbase = dil + ibase;
    float*       ebase = ero + ibase;

    const uint32_t s_st0 = (uint32_t)__cvta_generic_to_shared(stage0);
    const uint32_t s_st1 = (uint32_t)__cvta_generic_to_shared(stage1);
    const uint32_t s_mb0 = (uint32_t)__cvta_generic_to_shared(&mbar[0]);
    const uint32_t s_mb1 = (uint32_t)__cvta_generic_to_shared(&mbar[1]);

    if (tid == 0) {
        asm volatile("mbarrier.init.shared.b64 [%0], 1;" :: "r"(s_mb0));
        asm volatile("mbarrier.init.shared.b64 [%0], 1;" :: "r"(s_mb1));
    }
    __syncthreads();
    if (tid == 0) {
        bulk_load(s_st0, base + (size_t)y0a * W, s_mb0);
        bulk_load(s_st1, base + (size_t)y0b * W, s_mb1);
    }

    mbar_wait(s_mb0, 0);
    compute_chunk(stage0, r0a, y0a, x4, dbase, ebase);

    mbar_wait(s_mb1, 0);
    compute_chunk(stage1, r0b, y0b, x4, dbase, ebase);
}

extern "C" void kernel_launch(void* const* d_in, const int* in_sizes, int n_in,
                              void* d_out, int out_size)
{
    const float* x = (const float*)d_in[0];
    const int n = in_sizes[0];                  // 67108864
    const int nimg = n / (H * W);               // 256

    float* dil = (float*)d_out;
    float* ero = (float*)d_out + n;

    cudaFuncSetAttribute(erode_dilate_kernel,
                         cudaFuncAttributeMaxDynamicSharedMemorySize,
                         SMEM_TOTAL);

    const int nblocks = nimg * (H / (ROWS_OUT * 2));  // 4096
    erode_dilate_kernel<<<nblocks, THREADS, SMEM_TOTAL>>>(x, dil, ero);
}

// round 12
// speedup vs baseline: 1.0033x; 1.0033x over previous
#include <cuda_runtime.h>
#include <cstdint>

// Fused 3x3 dilate (max) + erode (min), fp32, (8,32,512,512) NCHW.
// Border: reduce over valid pixels only (replication == +/-inf pad).
// Output: [dilated | eroded], each 67108864 floats.
//
// R12: 4-deep read ring, guard-free (hedged rewrite of the twice-
// infra-failed R10 depth experiment).
//  - Each block owns 4 consecutive chunks of ONE image (8 out rows each,
//    16 quads per image): grid = 4096 exactly, no boundary guards.
//  - All four 20KB cp.async.bulk reads issued at block start into 4
//    statically-unrolled stages -> up to 3 copies pending during compute.
//  - 82KB dynamic smem -> 2 blocks/SM.
//  - Compute: rolling 3-row register window over smem rows; true left/
//    right neighbors from smem; edge replication (neutral for min/max);
//    streaming float4 stores.

#define W 512
#define H 512
#define ROWS_OUT 8
#define ROWS_IN  10
#define THREADS 128
#define CPB 4
#define STAGE_FLOATS (ROWS_IN * W)              // 5120
#define STAGE_BYTES  (STAGE_FLOATS * 4)         // 20480
#define SMEM_TOTAL   (CPB * STAGE_BYTES + 64)   // 81984

extern __shared__ float smem_pool[];

__device__ __forceinline__ void stcs4(float* p, float4 v) {
    asm volatile("st.global.cs.v4.f32 [%0], {%1,%2,%3,%4};"
                 :: "l"(p), "f"(v.x), "f"(v.y), "f"(v.z), "f"(v.w) : "memory");
}

__device__ __forceinline__ void mbar_wait0(uint32_t mbar) {
    asm volatile(
        "{\n\t"
        ".reg .pred P;\n\t"
        "WAIT_%=:\n\t"
        "mbarrier.try_wait.parity.shared.b64 P, [%0], 0, 10000000;\n\t"
        "@P bra.uni DONE_%=;\n\t"
        "bra.uni WAIT_%=;\n\t"
        "DONE_%=:\n\t"
        "}"
        :: "r"(mbar) : "memory");
}

__device__ __forceinline__ void bulk_load(uint32_t s_data, const float* src,
                                          uint32_t s_mbar) {
    asm volatile("mbarrier.arrive.expect_tx.shared.b64 _, [%0], %1;"
                 :: "r"(s_mbar), "r"((uint32_t)STAGE_BYTES));
    asm volatile(
        "cp.async.bulk.shared::cluster.global.mbarrier::complete_tx::bytes "
        "[%0], [%1], %2, [%3];"
        :: "r"(s_data), "l"(src), "r"((uint32_t)STAGE_BYTES), "r"(s_mbar)
        : "memory");
}

// local row-chunk index within image (0..63) -> clamped input start row
__device__ __forceinline__ int clamp_y0(int r0) {
    int y0 = r0 - 1;
    if (y0 < 0) y0 = 0;
    if (y0 > H - ROWS_IN) y0 = H - ROWS_IN;
    return y0;
}

__device__ __forceinline__ void compute_chunk(const float* __restrict__ buf,
                                              int r0, int x4,
                                              float* __restrict__ dbase,
                                              float* __restrict__ ebase)
{
    const int y0 = clamp_y0(r0);

    auto read_row = [&](int si, float4& v, float& lv, float& rv) {
        const float* rp = buf + si * W;
        v  = *reinterpret_cast<const float4*>(rp + x4);
        lv = (x4 > 0)     ? rp[x4 - 1] : v.x;   // replicate at image edge
        rv = (x4 + 4 < W) ? rp[x4 + 4] : v.w;
    };

    float4 pv, cv, nv;
    float plv, prv, clv, crv, nlv, nrv;

    int sp = r0 - 1 - y0; if (sp < 0) sp = 0;       // replicate top row
    read_row(sp,      pv, plv, prv);
    read_row(r0 - y0, cv, clv, crv);

    float* drow = dbase + (size_t)r0 * W + x4;
    float* erow = ebase + (size_t)r0 * W + x4;

    #pragma unroll
    for (int i = 0; i < ROWS_OUT; ++i) {
        int sn = r0 + i + 1 - y0;
        if (sn > ROWS_IN - 1) sn = ROWS_IN - 1;     // replicate bottom row
        read_row(sn, nv, nlv, nrv);

        float4 vmn, vmx;
        vmn.x = fminf(pv.x, fminf(cv.x, nv.x));
        vmn.y = fminf(pv.y, fminf(cv.y, nv.y));
        vmn.z = fminf(pv.z, fminf(cv.z, nv.z));
        vmn.w = fminf(pv.w, fminf(cv.w, nv.w));
        vmx.x = fmaxf(pv.x, fmaxf(cv.x, nv.x));
        vmx.y = fmaxf(pv.y, fmaxf(cv.y, nv.y));
        vmx.z = fmaxf(pv.z, fmaxf(cv.z, nv.z));
        vmx.w = fmaxf(pv.w, fmaxf(cv.w, nv.w));

        const float vl_mn = fminf(plv, fminf(clv, nlv));
        const float vl_mx = fmaxf(plv, fmaxf(clv, nlv));
        const float vr_mn = fminf(prv, fminf(crv, nrv));
        const float vr_mx = fmaxf(prv, fmaxf(crv, nrv));

        float4 omin, omax;
        omin.x = fminf(vl_mn, fminf(vmn.x, vmn.y));
        omin.y = fminf(vmn.x, fminf(vmn.y, vmn.z));
        omin.z = fminf(vmn.y, fminf(vmn.z, vmn.w));
        omin.w = fminf(vmn.z, fminf(vmn.w, vr_mn));

        omax.x = fmaxf(vl_mx, fmaxf(vmx.x, vmx.y));
        omax.y = fmaxf(vmx.x, fmaxf(vmx.y, vmx.z));
        omax.z = fmaxf(vmx.y, fmaxf(vmx.z, vmx.w));
        omax.w = fmaxf(vmx.z, fmaxf(vmx.w, vr_mx));

        stcs4(drow, omax);
        stcs4(erow, omin);
        drow += W;
        erow += W;

        pv = cv; cv = nv;
        plv = clv; clv = nlv;
        prv = crv; crv = nrv;
    }
}

__global__ __launch_bounds__(THREADS)
void erode_dilate_kernel(const float* __restrict__ in,
                         float* __restrict__ dil,
                         float* __restrict__ ero)
{
    float* st0 = smem_pool;
    float* st1 = smem_pool + 1 * STAGE_FLOATS;
    float* st2 = smem_pool + 2 * STAGE_FLOATS;
    float* st3 = smem_pool + 3 * STAGE_FLOATS;
    uint64_t* mbar = (uint64_t*)(smem_pool + CPB * STAGE_FLOATS);

    const int tid = threadIdx.x;
    const int x4  = tid * 4;
    const int bid = blockIdx.x;

    // 4 consecutive 8-row chunks of one image; 16 quads per image
    const int img = bid >> 4;
    const int r0  = (bid & 15) * (ROWS_OUT * CPB);

    const size_t ibase = (size_t)img * (H * W);
    const float* base  = in  + ibase;
    float*       dbase = dil + ibase;
    float*       ebase = ero + ibase;

    const uint32_t s_st0 = (uint32_t)__cvta_generic_to_shared(st0);
    const uint32_t s_st1 = (uint32_t)__cvta_generic_to_shared(st1);
    const uint32_t s_st2 = (uint32_t)__cvta_generic_to_shared(st2);
    const uint32_t s_st3 = (uint32_t)__cvta_generic_to_shared(st3);
    const uint32_t s_mb0 = (uint32_t)__cvta_generic_to_shared(&mbar[0]);
    const uint32_t s_mb1 = (uint32_t)__cvta_generic_to_shared(&mbar[1]);
    const uint32_t s_mb2 = (uint32_t)__cvta_generic_to_shared(&mbar[2]);
    const uint32_t s_mb3 = (uint32_t)__cvta_generic_to_shared(&mbar[3]);

    if (tid == 0) {
        asm volatile("mbarrier.init.shared.b64 [%0], 1;" :: "r"(s_mb0));
        asm volatile("mbarrier.init.shared.b64 [%0], 1;" :: "r"(s_mb1));
        asm volatile("mbarrier.init.shared.b64 [%0], 1;" :: "r"(s_mb2));
        asm volatile("mbarrier.init.shared.b64 [%0], 1;" :: "r"(s_mb3));
    }
    __syncthreads();
    if (tid == 0) {
        bulk_load(s_st0, base + (size_t)clamp_y0(r0               ) * W, s_mb0);
        bulk_load(s_st1, base + (size_t)clamp_y0(r0 + 1 * ROWS_OUT) * W, s_mb1);
        bulk_load(s_st2, base + (size_t)clamp_y0(r0 + 2 * ROWS_OUT) * W, s_mb2);
        bulk_load(s_st3, base + (size_t)clamp_y0(r0 + 3 * ROWS_OUT) * W, s_mb3);
    }

    mbar_wait0(s_mb0);
    compute_chunk(st0, r0,                x4, dbase, ebase);
    mbar_wait0(s_mb1);
    compute_chunk(st1, r0 + 1 * ROWS_OUT, x4, dbase, ebase);
    mbar_wait0(s_mb2);
    compute_chunk(st2, r0 + 2 * ROWS_OUT, x4, dbase, ebase);
    mbar_wait0(s_mb3);
    compute_chunk(st3, r0 + 3 * ROWS_OUT, x4, dbase, ebase);
}

extern "C" void kernel_launch(void* const* d_in, const int* in_sizes, int n_in,
                              void* d_out, int out_size)
{
    const float* x = (const float*)d_in[0];
    const int n = in_sizes[0];                  // 67108864
    const int nimg = n / (H * W);               // 256

    float* dil = (float*)d_out;
    float* ero = (float*)d_out + n;

    cudaFuncSetAttribute(erode_dilate_kernel,
                         cudaFuncAttributeMaxDynamicSharedMemorySize,
                         SMEM_TOTAL);

    const int nblocks = nimg * (H / (ROWS_OUT * CPB));  // 4096
    erode_dilate_kernel<<<nblocks, THREADS, SMEM_TOTAL>>>(x, dil, ero);
}